// round 1
// baseline (speedup 1.0000x reference)
#include <cuda_runtime.h>

#define BATCH 16
#define NT 3
#define NSEQ 1024
#define IND 512
#define FD 256
#define NLAY 3
#define NWRD 32
#define ALPHAV 0.2f
#define NEGV -9e15f

// ---------------- scratch (device globals; no allocations allowed) ----------
__device__ unsigned g_mask[NLAY][BATCH * NT * NSEQ * NWRD];     // boolean adj^k > 0
__device__ float g_h[(size_t)9 * BATCH * NSEQ * FD];            // h[t*3+k][b][n][f]
__device__ float g_f1[9 * BATCH * NSEQ];
__device__ float g_f2[9 * BATCH * NSEQ];
__device__ float g_att[(size_t)BATCH * NSEQ * NSEQ];            // att for one (k,t)
__device__ float g_H[(size_t)BATCH * NSEQ * NLAY * FD];         // stacked layer outputs

// ---------------- adj -> bitset --------------------------------------------
__global__ void bits_kernel(const float* __restrict__ adj) {
    int r = blockIdx.x;                    // (b*3+t)*NSEQ + i
    int tid = threadIdx.x;                 // 1024
    float v = adj[(size_t)r * NSEQ + tid];
    unsigned bal = __ballot_sync(0xffffffffu, v > 0.0f);
    if ((tid & 31) == 0) g_mask[0][(size_t)r * NWRD + (tid >> 5)] = bal;
}

// boolean matmul: g_mask[dst] = g_mask[src] (x) g_mask[0]  (per (b,t) slice)
__global__ void bmm_kernel(int src, int dst) {
    int r = blockIdx.x;                    // global row
    int bt = r / NSEQ;                     // (b*3+t)
    int lane = threadIdx.x;                // 32
    const unsigned* lrow = &g_mask[src][(size_t)r * NWRD];
    const unsigned* rbase = &g_mask[0][(size_t)bt * NSEQ * NWRD];
    unsigned myw = lrow[lane];
    unsigned acc = 0;
    #pragma unroll 1
    for (int w = 0; w < NWRD; ++w) {
        unsigned bitsw = __shfl_sync(0xffffffffu, myw, w);
        while (bitsw) {
            int j = (w << 5) + (__ffs(bitsw) - 1);
            bitsw &= bitsw - 1;
            acc |= rbase[(size_t)j * NWRD + lane];
        }
    }
    g_mask[dst][(size_t)r * NWRD + lane] = acc;
}

// ---------------- generic strided-batched SGEMM (128x128x8, 256 thr) -------
// A [M,K] row-major, B [K,N] row-major, C [M,N] (ldc). All dims % tile == 0.
__global__ __launch_bounds__(256) void sgemm128(
    const float* __restrict__ A, const float* __restrict__ Bm, float* __restrict__ C,
    int M, int Nn, int Kk, int lda, int ldb, int ldc,
    long long sA, long long sB, long long sC, int accum)
{
    int z = blockIdx.z;
    A  += (size_t)z * sA;
    Bm += (size_t)z * sB;
    C  += (size_t)z * sC;

    __shared__ float As[8][128];
    __shared__ float Bs[8][128];

    int tid = threadIdx.x;
    int bm = blockIdx.y * 128, bn = blockIdx.x * 128;
    int aRow = tid >> 1,  aCol = (tid & 1) * 4;
    int bRow = tid >> 5,  bCol = (tid & 31) * 4;
    int ty = tid >> 4,    tx = tid & 15;    // 8x8 micro-tile at (ty*8, tx*8)

    float acc[8][8];
    #pragma unroll
    for (int i = 0; i < 8; i++)
        #pragma unroll
        for (int j = 0; j < 8; j++) acc[i][j] = 0.0f;

    for (int k0 = 0; k0 < Kk; k0 += 8) {
        float4 av = *(const float4*)(A  + (size_t)(bm + aRow) * lda + k0 + aCol);
        float4 bv = *(const float4*)(Bm + (size_t)(k0 + bRow) * ldb + bn + bCol);
        __syncthreads();
        As[aCol + 0][aRow] = av.x;
        As[aCol + 1][aRow] = av.y;
        As[aCol + 2][aRow] = av.z;
        As[aCol + 3][aRow] = av.w;
        *(float4*)(&Bs[bRow][bCol]) = bv;
        __syncthreads();
        #pragma unroll
        for (int kk = 0; kk < 8; kk++) {
            float4 a0 = *(const float4*)(&As[kk][ty * 8]);
            float4 a1v = *(const float4*)(&As[kk][ty * 8 + 4]);
            float4 b0 = *(const float4*)(&Bs[kk][tx * 8]);
            float4 b1 = *(const float4*)(&Bs[kk][tx * 8 + 4]);
            float ar[8] = {a0.x, a0.y, a0.z, a0.w, a1v.x, a1v.y, a1v.z, a1v.w};
            float br[8] = {b0.x, b0.y, b0.z, b0.w, b1.x, b1.y, b1.z, b1.w};
            #pragma unroll
            for (int i = 0; i < 8; i++)
                #pragma unroll
                for (int j = 0; j < 8; j++)
                    acc[i][j] = fmaf(ar[i], br[j], acc[i][j]);
        }
    }

    #pragma unroll
    for (int i = 0; i < 8; i++) {
        float* cp = C + (size_t)(bm + ty * 8 + i) * ldc + bn + tx * 8;
        float4 v0 = make_float4(acc[i][0], acc[i][1], acc[i][2], acc[i][3]);
        float4 v1 = make_float4(acc[i][4], acc[i][5], acc[i][6], acc[i][7]);
        if (accum) {
            float4 o0 = ((const float4*)cp)[0];
            float4 o1 = ((const float4*)cp)[1];
            v0.x += o0.x; v0.y += o0.y; v0.z += o0.z; v0.w += o0.w;
            v1.x += o1.x; v1.y += o1.y; v1.z += o1.z; v1.w += o1.w;
        }
        ((float4*)cp)[0] = v0;
        ((float4*)cp)[1] = v1;
    }
}

// ---------------- f1/f2: h . a1, h . a2  (one warp per (z, bn)) -------------
__global__ void f_kernel(const float* __restrict__ a1, const float* __restrict__ a2) {
    int gw = (blockIdx.x * blockDim.x + threadIdx.x) >> 5;
    int lane = threadIdx.x & 31;
    if (gw >= 9 * BATCH * NSEQ) return;
    int z = gw / (BATCH * NSEQ);
    const float* hp = &g_h[(size_t)gw * FD];
    const float* a1p = a1 + (size_t)z * FD;
    const float* a2p = a2 + (size_t)z * FD;
    float s1 = 0.0f, s2 = 0.0f;
    #pragma unroll
    for (int i = lane; i < FD; i += 32) {
        float hv = hp[i];
        s1 = fmaf(hv, a1p[i], s1);
        s2 = fmaf(hv, a2p[i], s2);
    }
    #pragma unroll
    for (int off = 16; off > 0; off >>= 1) {
        s1 += __shfl_down_sync(0xffffffffu, s1, off);
        s2 += __shfl_down_sync(0xffffffffu, s2, off);
    }
    if (lane == 0) { g_f1[gw] = s1; g_f2[gw] = s2; }
}

// ---------------- masked-softmax attention row ------------------------------
// grid (NSEQ, BATCH), 256 threads; writes g_att[b][i][:]
__global__ void att_kernel(int t, int k) {
    int i = blockIdx.x, b = blockIdx.y;
    int tid = threadIdx.x;
    int z = t * 3 + k;

    __shared__ float sf2[NSEQ];
    __shared__ unsigned smask[NWRD];
    __shared__ float red[256];

    const float* f2p = &g_f2[(size_t)z * BATCH * NSEQ + (size_t)b * NSEQ];
    for (int j = tid; j < NSEQ; j += 256) sf2[j] = f2p[j];
    if (tid < NWRD)
        smask[tid] = g_mask[k][(((size_t)b * NT + t) * NSEQ + i) * NWRD + tid];
    __syncthreads();

    float f1v = g_f1[(size_t)z * BATCH * NSEQ + (size_t)b * NSEQ + i];

    float e[4];
    bool msk[4];
    float lmax = NEGV;
    #pragma unroll
    for (int q = 0; q < 4; q++) {
        int j = tid + q * 256;
        bool m = (smask[j >> 5] >> (j & 31)) & 1u;
        float x = f1v + sf2[j];
        x = (x > 0.0f) ? x : ALPHAV * x;
        e[q] = m ? x : NEGV;
        msk[q] = m;
        lmax = fmaxf(lmax, e[q]);
    }
    red[tid] = lmax;
    __syncthreads();
    for (int s = 128; s > 0; s >>= 1) {
        if (tid < s) red[tid] = fmaxf(red[tid], red[tid + s]);
        __syncthreads();
    }
    float m = red[0];
    __syncthreads();

    bool empty = (m < -8.9e15f);
    float p[4];
    float lsum = 0.0f;
    #pragma unroll
    for (int q = 0; q < 4; q++) {
        p[q] = empty ? 1.0f : (msk[q] ? __expf(e[q] - m) : 0.0f);
        lsum += p[q];
    }
    red[tid] = lsum;
    __syncthreads();
    for (int s = 128; s > 0; s >>= 1) {
        if (tid < s) red[tid] += red[tid + s];
        __syncthreads();
    }
    float inv = 1.0f / red[0];

    float* arow = &g_att[((size_t)b * NSEQ + i) * NSEQ];
    #pragma unroll
    for (int q = 0; q < 4; q++) arow[tid + q * 256] = p[q] * inv;
}

// ---------------- final combine: s=tanh(H@Ww+bw)@Wc, softmax over K --------
__global__ void combine_kernel(const float* __restrict__ Ww, const float* __restrict__ bw,
                               const float* __restrict__ Wc, float* __restrict__ out) {
    int bn = blockIdx.x;
    int tid = threadIdx.x;   // 128
    __shared__ float sh[NLAY * FD];
    __shared__ float part[NLAY][128];
    __shared__ float sy[NLAY];

    const float* Hp = &g_H[(size_t)bn * NLAY * FD];
    for (int i = tid; i < NLAY * FD; i += 128) sh[i] = Hp[i];
    __syncthreads();

    float loc[NLAY] = {0.0f, 0.0f, 0.0f};
    if (tid < 100) {
        float wc = Wc[tid];
        float bwv = bw[tid];
        #pragma unroll
        for (int k = 0; k < NLAY; k++) {
            float y = bwv;
            #pragma unroll 8
            for (int i = 0; i < FD; i++)
                y = fmaf(sh[k * FD + i], Ww[i * 100 + tid], y);
            loc[k] = tanhf(y) * wc;
        }
    }
    #pragma unroll
    for (int k = 0; k < NLAY; k++) part[k][tid] = loc[k];
    __syncthreads();
    for (int s = 64; s > 0; s >>= 1) {
        if (tid < s) {
            part[0][tid] += part[0][tid + s];
            part[1][tid] += part[1][tid + s];
            part[2][tid] += part[2][tid + s];
        }
        __syncthreads();
    }
    if (tid == 0) {
        float s0 = part[0][0], s1 = part[1][0], s2 = part[2][0];
        float mx = fmaxf(s0, fmaxf(s1, s2));
        float e0 = __expf(s0 - mx), e1 = __expf(s1 - mx), e2 = __expf(s2 - mx);
        float invs = 1.0f / (e0 + e1 + e2);
        sy[0] = e0 * invs; sy[1] = e1 * invs; sy[2] = e2 * invs;
    }
    __syncthreads();

    float w0 = sy[0], w1 = sy[1], w2 = sy[2];
    for (int f = tid; f < FD; f += 128)
        out[(size_t)bn * FD + f] =
            w0 * sh[f] + w1 * sh[FD + f] + w2 * sh[2 * FD + f];
}

// ---------------- launch ----------------------------------------------------
extern "C" void kernel_launch(void* const* d_in, const int* in_sizes, int n_in,
                              void* d_out, int out_size) {
    const float* adj = (const float*)d_in[0];
    const float* X   = (const float*)d_in[1];
    const float* W   = (const float*)d_in[2];
    const float* a1  = (const float*)d_in[3];
    const float* a2  = (const float*)d_in[4];
    const float* Ww  = (const float*)d_in[5];
    const float* bw  = (const float*)d_in[6];
    const float* Wc  = (const float*)d_in[7];
    float* out = (float*)d_out;

    void *ph, *patt, *pH;
    cudaGetSymbolAddress(&ph, g_h);
    cudaGetSymbolAddress(&patt, g_att);
    cudaGetSymbolAddress(&pH, g_H);
    float* hbuf = (float*)ph;
    float* attbuf = (float*)patt;
    float* Hbuf = (float*)pH;

    // 1. adjacency bitsets + boolean powers (mask-only — values never needed)
    bits_kernel<<<BATCH * NT * NSEQ, 1024>>>(adj);
    bmm_kernel<<<BATCH * NT * NSEQ, 32>>>(0, 1);   // adj^2 > 0
    bmm_kernel<<<BATCH * NT * NSEQ, 32>>>(1, 2);   // adj^3 > 0

    // 2. h[t,k] = X @ W[t,k]  for all 9 (t,k)
    {
        dim3 grid(FD / 128, (BATCH * NSEQ) / 128, 9);
        sgemm128<<<grid, 256>>>(X, W, hbuf,
                                BATCH * NSEQ, FD, IND,
                                IND, FD, FD,
                                0LL, (long long)IND * FD,
                                (long long)BATCH * NSEQ * FD, 0);
    }

    // 3. f1/f2 projections
    f_kernel<<<(9 * BATCH * NSEQ) / 8, 256>>>(a1, a2);

    // 4. per layer k, per relation t: masked softmax + att@h accumulated into H
    for (int k = 0; k < NLAY; k++) {
        for (int t = 0; t < NT; t++) {
            att_kernel<<<dim3(NSEQ, BATCH), 256>>>(t, k);
            int z = t * 3 + k;
            dim3 grid(FD / 128, NSEQ / 128, BATCH);
            sgemm128<<<grid, 256>>>(attbuf,
                                    hbuf + (size_t)z * BATCH * NSEQ * FD,
                                    Hbuf + k * FD,
                                    NSEQ, FD, NSEQ,
                                    NSEQ, FD, NLAY * FD,
                                    (long long)NSEQ * NSEQ,
                                    (long long)NSEQ * FD,
                                    (long long)NSEQ * NLAY * FD,
                                    t > 0 ? 1 : 0);
        }
    }

    // 5. combine
    combine_kernel<<<BATCH * NSEQ, 128>>>(Ww, bw, Wc, out);
}

// round 2
// speedup vs baseline: 1.3793x; 1.3793x over previous
#include <cuda_runtime.h>

#define BATCH 16
#define NT 3
#define NSEQ 1024
#define IND 512
#define FD 256
#define NLAY 3
#define NWRD 32
#define ALPHAV 0.2f
#define NEGV -9e15f

// ---------------- scratch (device globals; no allocations allowed) ----------
__device__ unsigned g_mask[NLAY][BATCH * NT * NSEQ * NWRD];     // boolean adj^k > 0
__device__ float g_h[(size_t)9 * BATCH * NSEQ * FD];            // h[t*3+k][b][n][f]
__device__ float g_f1[9 * BATCH * NSEQ];
__device__ float g_f2[9 * BATCH * NSEQ];
__device__ float g_att[(size_t)BATCH * NSEQ * NSEQ];            // att for one (k,t)
__device__ float g_H[(size_t)BATCH * NSEQ * NLAY * FD];         // stacked layer outputs

// ---------------- adj -> bitset --------------------------------------------
__global__ void bits_kernel(const float* __restrict__ adj) {
    int r = blockIdx.x;                    // (b*3+t)*NSEQ + i
    int tid = threadIdx.x;                 // 1024
    float v = adj[(size_t)r * NSEQ + tid];
    unsigned bal = __ballot_sync(0xffffffffu, v > 0.0f);
    if ((tid & 31) == 0) g_mask[0][(size_t)r * NWRD + (tid >> 5)] = bal;
}

// boolean matmul: g_mask[dst] = g_mask[src] (x) g_mask[0]  (per (b,t) slice)
__global__ void bmm_kernel(int src, int dst) {
    int r = blockIdx.x;                    // global row
    int bt = r / NSEQ;                     // (b*3+t)
    int lane = threadIdx.x;                // 32
    const unsigned* lrow = &g_mask[src][(size_t)r * NWRD];
    const unsigned* rbase = &g_mask[0][(size_t)bt * NSEQ * NWRD];
    unsigned myw = lrow[lane];
    unsigned acc = 0;
    #pragma unroll 1
    for (int w = 0; w < NWRD; ++w) {
        unsigned bitsw = __shfl_sync(0xffffffffu, myw, w);
        while (bitsw) {
            int j = (w << 5) + (__ffs(bitsw) - 1);
            bitsw &= bitsw - 1;
            acc |= rbase[(size_t)j * NWRD + lane];
        }
    }
    g_mask[dst][(size_t)r * NWRD + lane] = acc;
}

// ---------------- double-buffered strided-batched SGEMM (128x128x8) --------
__global__ __launch_bounds__(256) void sgemm128(
    const float* __restrict__ A, const float* __restrict__ Bm, float* __restrict__ C,
    int M, int Nn, int Kk, int lda, int ldb, int ldc,
    long long sA, long long sB, long long sC, int accum)
{
    int z = blockIdx.z;
    A  += (size_t)z * sA;
    Bm += (size_t)z * sB;
    C  += (size_t)z * sC;

    __shared__ float As[2][8][128];
    __shared__ float Bs[2][8][128];

    int tid = threadIdx.x;
    int bm = blockIdx.y * 128, bn = blockIdx.x * 128;
    int aRow = tid >> 1,  aCol = (tid & 1) * 4;
    int bRow = tid >> 5,  bCol = (tid & 31) * 4;
    int ty = tid >> 4,    tx = tid & 15;

    const float* Aptr = A  + (size_t)(bm + aRow) * lda + aCol;
    const float* Bptr = Bm + (size_t)bRow * ldb + bn + bCol;

    float4 av = *(const float4*)Aptr;
    float4 bv = *(const float4*)Bptr;
    As[0][aCol + 0][aRow] = av.x;
    As[0][aCol + 1][aRow] = av.y;
    As[0][aCol + 2][aRow] = av.z;
    As[0][aCol + 3][aRow] = av.w;
    *(float4*)(&Bs[0][bRow][bCol]) = bv;
    __syncthreads();

    float acc[8][8];
    #pragma unroll
    for (int i = 0; i < 8; i++)
        #pragma unroll
        for (int j = 0; j < 8; j++) acc[i][j] = 0.0f;

    int nIter = Kk >> 3;
    for (int it = 0; it < nIter; it++) {
        int cur = it & 1;
        if (it + 1 < nIter) {
            av = *(const float4*)(Aptr + (it + 1) * 8);
            bv = *(const float4*)(Bptr + (size_t)(it + 1) * 8 * ldb);
        }
        #pragma unroll
        for (int kk = 0; kk < 8; kk++) {
            float4 a0  = *(const float4*)(&As[cur][kk][ty * 8]);
            float4 a1v = *(const float4*)(&As[cur][kk][ty * 8 + 4]);
            float4 b0  = *(const float4*)(&Bs[cur][kk][tx * 8]);
            float4 b1  = *(const float4*)(&Bs[cur][kk][tx * 8 + 4]);
            float ar[8] = {a0.x, a0.y, a0.z, a0.w, a1v.x, a1v.y, a1v.z, a1v.w};
            float br[8] = {b0.x, b0.y, b0.z, b0.w, b1.x, b1.y, b1.z, b1.w};
            #pragma unroll
            for (int i = 0; i < 8; i++)
                #pragma unroll
                for (int j = 0; j < 8; j++)
                    acc[i][j] = fmaf(ar[i], br[j], acc[i][j]);
        }
        if (it + 1 < nIter) {
            int nxt = cur ^ 1;
            As[nxt][aCol + 0][aRow] = av.x;
            As[nxt][aCol + 1][aRow] = av.y;
            As[nxt][aCol + 2][aRow] = av.z;
            As[nxt][aCol + 3][aRow] = av.w;
            *(float4*)(&Bs[nxt][bRow][bCol]) = bv;
            __syncthreads();
        }
    }

    #pragma unroll
    for (int i = 0; i < 8; i++) {
        float* cp = C + (size_t)(bm + ty * 8 + i) * ldc + bn + tx * 8;
        float4 v0 = make_float4(acc[i][0], acc[i][1], acc[i][2], acc[i][3]);
        float4 v1 = make_float4(acc[i][4], acc[i][5], acc[i][6], acc[i][7]);
        if (accum) {
            float4 o0 = ((const float4*)cp)[0];
            float4 o1 = ((const float4*)cp)[1];
            v0.x += o0.x; v0.y += o0.y; v0.z += o0.z; v0.w += o0.w;
            v1.x += o1.x; v1.y += o1.y; v1.z += o1.z; v1.w += o1.w;
        }
        ((float4*)cp)[0] = v0;
        ((float4*)cp)[1] = v1;
    }
}

// ---------------- f1/f2: h . a1, h . a2  ------------------------------------
__global__ void f_kernel(const float* __restrict__ a1, const float* __restrict__ a2) {
    int gw = (blockIdx.x * blockDim.x + threadIdx.x) >> 5;
    int lane = threadIdx.x & 31;
    if (gw >= 9 * BATCH * NSEQ) return;
    int z = gw / (BATCH * NSEQ);
    const float* hp = &g_h[(size_t)gw * FD];
    const float* a1p = a1 + (size_t)z * FD;
    const float* a2p = a2 + (size_t)z * FD;
    float s1 = 0.0f, s2 = 0.0f;
    #pragma unroll
    for (int i = lane; i < FD; i += 32) {
        float hv = hp[i];
        s1 = fmaf(hv, a1p[i], s1);
        s2 = fmaf(hv, a2p[i], s2);
    }
    #pragma unroll
    for (int off = 16; off > 0; off >>= 1) {
        s1 += __shfl_down_sync(0xffffffffu, s1, off);
        s2 += __shfl_down_sync(0xffffffffu, s2, off);
    }
    if (lane == 0) { g_f1[gw] = s1; g_f2[gw] = s2; }
}

// ---------------- fused sparse softmax + SpMM (layers k=0,1) ----------------
// one block per (b, row n); loops the 3 relations; writes H[b][n][k][:]
__global__ __launch_bounds__(256) void spmm_kernel(int k, float* __restrict__ Hout) {
    int n = blockIdx.x, b = blockIdx.y;
    int tid = threadIdx.x;

    __shared__ int   list[NSEQ];
    __shared__ float pn[NSEQ];
    __shared__ int   s_cnt;
    __shared__ float red[256];

    float acc = 0.0f;                 // accumulation for feature f = tid

    for (int t = 0; t < NT; t++) {
        int z = t * 3 + k;
        if (tid == 0) s_cnt = 0;
        __syncthreads();
        if (tid < NWRD) {
            unsigned w = g_mask[k][(((size_t)b * NT + t) * NSEQ + n) * NWRD + tid];
            while (w) {
                int j = (tid << 5) + (__ffs(w) - 1);
                w &= w - 1;
                int p = atomicAdd(&s_cnt, 1);
                list[p] = j;
            }
        }
        __syncthreads();
        int cnt = s_cnt;

        const float* f2p = &g_f2[(size_t)z * BATCH * NSEQ + (size_t)b * NSEQ];
        float f1v = g_f1[(size_t)z * BATCH * NSEQ + (size_t)b * NSEQ + n];
        const float* hp = &g_h[((size_t)z * BATCH + b) * NSEQ * FD];

        if (cnt == 0) {
            // all-masked row -> uniform attention over all NSEQ
            float a = 0.0f;
            for (int j = 0; j < NSEQ; j++) a += hp[(size_t)j * FD + tid];
            acc += a * (1.0f / NSEQ);
            __syncthreads();
            continue;
        }

        // e values + max
        float lmax = -1e30f;
        for (int i = tid; i < cnt; i += 256) {
            float x = f1v + f2p[list[i]];
            x = (x > 0.0f) ? x : ALPHAV * x;
            pn[i] = x;
            lmax = fmaxf(lmax, x);
        }
        red[tid] = lmax;
        __syncthreads();
        for (int s = 128; s > 0; s >>= 1) {
            if (tid < s) red[tid] = fmaxf(red[tid], red[tid + s]);
            __syncthreads();
        }
        float m = red[0];
        __syncthreads();

        float lsum = 0.0f;
        for (int i = tid; i < cnt; i += 256) {
            float p = __expf(pn[i] - m);
            pn[i] = p;
            lsum += p;
        }
        red[tid] = lsum;
        __syncthreads();
        for (int s = 128; s > 0; s >>= 1) {
            if (tid < s) red[tid] += red[tid + s];
            __syncthreads();
        }
        float inv = 1.0f / red[0];
        __syncthreads();

        // gather-accumulate: each thread owns feature f = tid
        int i = 0;
        for (; i + 4 <= cnt; i += 4) {
            int j0 = list[i], j1 = list[i + 1], j2 = list[i + 2], j3 = list[i + 3];
            float p0 = pn[i] * inv, p1 = pn[i + 1] * inv;
            float p2 = pn[i + 2] * inv, p3 = pn[i + 3] * inv;
            float h0 = hp[(size_t)j0 * FD + tid];
            float h1 = hp[(size_t)j1 * FD + tid];
            float h2 = hp[(size_t)j2 * FD + tid];
            float h3 = hp[(size_t)j3 * FD + tid];
            acc = fmaf(p0, h0, acc);
            acc = fmaf(p1, h1, acc);
            acc = fmaf(p2, h2, acc);
            acc = fmaf(p3, h3, acc);
        }
        for (; i < cnt; i++)
            acc = fmaf(pn[i] * inv, hp[(size_t)list[i] * FD + tid], acc);
        __syncthreads();   // protect list/pn before next relation rewrites them
    }

    Hout[(((size_t)b * NSEQ + n) * NLAY + k) * FD + tid] = acc;
}

// ---------------- dense masked-softmax attention row (k=2) ------------------
__global__ void att_kernel(int t, int k) {
    int i = blockIdx.x, b = blockIdx.y;
    int tid = threadIdx.x;
    int z = t * 3 + k;

    __shared__ float sf2[NSEQ];
    __shared__ unsigned smask[NWRD];
    __shared__ float red[256];

    const float* f2p = &g_f2[(size_t)z * BATCH * NSEQ + (size_t)b * NSEQ];
    for (int j = tid; j < NSEQ; j += 256) sf2[j] = f2p[j];
    if (tid < NWRD)
        smask[tid] = g_mask[k][(((size_t)b * NT + t) * NSEQ + i) * NWRD + tid];
    __syncthreads();

    float f1v = g_f1[(size_t)z * BATCH * NSEQ + (size_t)b * NSEQ + i];

    float e[4];
    bool msk[4];
    float lmax = NEGV;
    #pragma unroll
    for (int q = 0; q < 4; q++) {
        int j = tid + q * 256;
        bool m = (smask[j >> 5] >> (j & 31)) & 1u;
        float x = f1v + sf2[j];
        x = (x > 0.0f) ? x : ALPHAV * x;
        e[q] = m ? x : NEGV;
        msk[q] = m;
        lmax = fmaxf(lmax, e[q]);
    }
    red[tid] = lmax;
    __syncthreads();
    for (int s = 128; s > 0; s >>= 1) {
        if (tid < s) red[tid] = fmaxf(red[tid], red[tid + s]);
        __syncthreads();
    }
    float m = red[0];
    __syncthreads();

    bool empty = (m < -8.9e15f);
    float p[4];
    float lsum = 0.0f;
    #pragma unroll
    for (int q = 0; q < 4; q++) {
        p[q] = empty ? 1.0f : (msk[q] ? __expf(e[q] - m) : 0.0f);
        lsum += p[q];
    }
    red[tid] = lsum;
    __syncthreads();
    for (int s = 128; s > 0; s >>= 1) {
        if (tid < s) red[tid] += red[tid + s];
        __syncthreads();
    }
    float inv = 1.0f / red[0];

    float* arow = &g_att[((size_t)b * NSEQ + i) * NSEQ];
    #pragma unroll
    for (int q = 0; q < 4; q++) arow[tid + q * 256] = p[q] * inv;
}

// ---------------- final combine ---------------------------------------------
__global__ void combine_kernel(const float* __restrict__ Ww, const float* __restrict__ bw,
                               const float* __restrict__ Wc, float* __restrict__ out) {
    int bn = blockIdx.x;
    int tid = threadIdx.x;   // 128
    __shared__ float sh[NLAY * FD];
    __shared__ float part[NLAY][128];
    __shared__ float sy[NLAY];

    const float* Hp = &g_H[(size_t)bn * NLAY * FD];
    for (int i = tid; i < NLAY * FD; i += 128) sh[i] = Hp[i];
    __syncthreads();

    float loc[NLAY] = {0.0f, 0.0f, 0.0f};
    if (tid < 100) {
        float wc = Wc[tid];
        float bwv = bw[tid];
        #pragma unroll
        for (int k = 0; k < NLAY; k++) {
            float y = bwv;
            #pragma unroll 8
            for (int i = 0; i < FD; i++)
                y = fmaf(sh[k * FD + i], Ww[i * 100 + tid], y);
            loc[k] = tanhf(y) * wc;
        }
    }
    #pragma unroll
    for (int k = 0; k < NLAY; k++) part[k][tid] = loc[k];
    __syncthreads();
    for (int s = 64; s > 0; s >>= 1) {
        if (tid < s) {
            part[0][tid] += part[0][tid + s];
            part[1][tid] += part[1][tid + s];
            part[2][tid] += part[2][tid + s];
        }
        __syncthreads();
    }
    if (tid == 0) {
        float s0 = part[0][0], s1 = part[1][0], s2 = part[2][0];
        float mx = fmaxf(s0, fmaxf(s1, s2));
        float e0 = __expf(s0 - mx), e1 = __expf(s1 - mx), e2 = __expf(s2 - mx);
        float invs = 1.0f / (e0 + e1 + e2);
        sy[0] = e0 * invs; sy[1] = e1 * invs; sy[2] = e2 * invs;
    }
    __syncthreads();

    float w0 = sy[0], w1 = sy[1], w2 = sy[2];
    for (int f = tid; f < FD; f += 128)
        out[(size_t)bn * FD + f] =
            w0 * sh[f] + w1 * sh[FD + f] + w2 * sh[2 * FD + f];
}

// ---------------- launch ----------------------------------------------------
extern "C" void kernel_launch(void* const* d_in, const int* in_sizes, int n_in,
                              void* d_out, int out_size) {
    const float* adj = (const float*)d_in[0];
    const float* X   = (const float*)d_in[1];
    const float* W   = (const float*)d_in[2];
    const float* a1  = (const float*)d_in[3];
    const float* a2  = (const float*)d_in[4];
    const float* Ww  = (const float*)d_in[5];
    const float* bw  = (const float*)d_in[6];
    const float* Wc  = (const float*)d_in[7];
    float* out = (float*)d_out;

    void *ph, *patt, *pH;
    cudaGetSymbolAddress(&ph, g_h);
    cudaGetSymbolAddress(&patt, g_att);
    cudaGetSymbolAddress(&pH, g_H);
    float* hbuf = (float*)ph;
    float* attbuf = (float*)patt;
    float* Hbuf = (float*)pH;

    // 1. adjacency bitsets + boolean powers (mask-only)
    bits_kernel<<<BATCH * NT * NSEQ, 1024>>>(adj);
    bmm_kernel<<<BATCH * NT * NSEQ, 32>>>(0, 1);   // adj^2 > 0
    bmm_kernel<<<BATCH * NT * NSEQ, 32>>>(1, 2);   // adj^3 > 0

    // 2. h[t,k] = X @ W[t,k]  for all 9 (t,k)
    {
        dim3 grid(FD / 128, (BATCH * NSEQ) / 128, 9);
        sgemm128<<<grid, 256>>>(X, W, hbuf,
                                BATCH * NSEQ, FD, IND,
                                IND, FD, FD,
                                0LL, (long long)IND * FD,
                                (long long)BATCH * NSEQ * FD, 0);
    }

    // 3. f1/f2 projections
    f_kernel<<<(9 * BATCH * NSEQ) / 8, 256>>>(a1, a2);

    // 4a. sparse layers k=0,1: fused softmax + SpMM
    spmm_kernel<<<dim3(NSEQ, BATCH), 256>>>(0, Hbuf);
    spmm_kernel<<<dim3(NSEQ, BATCH), 256>>>(1, Hbuf);

    // 4b. dense layer k=2: masked softmax + dense GEMM, accumulated over t
    for (int t = 0; t < NT; t++) {
        att_kernel<<<dim3(NSEQ, BATCH), 256>>>(t, 2);
        int z = t * 3 + 2;
        dim3 grid(FD / 128, NSEQ / 128, BATCH);
        sgemm128<<<grid, 256>>>(attbuf,
                                hbuf + (size_t)z * BATCH * NSEQ * FD,
                                Hbuf + 2 * FD,
                                NSEQ, FD, NSEQ,
                                NSEQ, FD, NLAY * FD,
                                (long long)NSEQ * NSEQ,
                                (long long)NSEQ * FD,
                                (long long)NSEQ * NLAY * FD,
                                t > 0 ? 1 : 0);
    }

    // 5. combine
    combine_kernel<<<BATCH * NSEQ, 128>>>(Ww, bw, Wc, out);
}